// round 2
// baseline (speedup 1.0000x reference)
#include <cuda_runtime.h>
#include <math.h>

// Model dims
#define TT   2048
#define DD   512
#define HH   8
#define HDD  64
#define LLAY 4
#define HIDN 2048
#define EE   8
#define KEXP 2
#define VV   32000

typedef long long ll;

// ----------------------------------------------------------------------------
// Device scratch (static __device__ arrays: allocation-free, harness-legal)
// ----------------------------------------------------------------------------
__device__ float g_x[TT * DD];
__device__ float g_xn[TT * DD];
__device__ float g_q[TT * DD];
__device__ float g_k[TT * DD];
__device__ float g_v[TT * DD];
__device__ float g_attn[TT * DD];
__device__ float g_P[33554432];            // H*T*T = 8*2048*2048
__device__ float g_G[TT * KEXP * HIDN];    // 4096 x 2048
__device__ float g_U[TT * KEXP * HIDN];
__device__ float g_Y[TT * KEXP * DD];
__device__ float g_ew[TT * KEXP];
__device__ int   g_eidx[TT * KEXP];
__device__ int   g_counts[EE];
__device__ int   g_offs[EE];
__device__ int   g_cursor[EE];
__device__ int   g_perm[TT * KEXP];
__device__ int   g_slot[TT * KEXP];

// ----------------------------------------------------------------------------
// Generic batched SGEMM: C = A @ B (or A @ B^T), optional residual add.
// 128x128 block tile, BK=8, 256 threads, 8x8 microtile. K must be %8==0.
// causal: skip tiles strictly above diagonal (for attention scores).
// ----------------------------------------------------------------------------
template <bool TRANSB>
__global__ __launch_bounds__(256) void sgemm_kernel(
    const float* __restrict__ A, int lda, ll sA,
    const float* __restrict__ B, int ldb, ll sB,
    float* __restrict__ C, int ldc, ll sC,
    const float* __restrict__ Res,
    int M, int N, int K, int causal)
{
    if (causal && (int)blockIdx.x > (int)blockIdx.y) return;

    const float* Ab = A + (ll)blockIdx.z * sA;
    const float* Bb = B + (ll)blockIdx.z * sB;
    float*       Cb = C + (ll)blockIdx.z * sC;
    const float* Rb = Res ? (Res + (ll)blockIdx.z * sC) : (const float*)0;

    const int bm = blockIdx.y * 128;
    const int bn = blockIdx.x * 128;
    const int tid = threadIdx.x;
    const int tx = tid & 15, ty = tid >> 4;

    __shared__ float As[8][128];
    __shared__ float Bs[8][128];

    float acc[8][8];
#pragma unroll
    for (int i = 0; i < 8; i++)
#pragma unroll
        for (int j = 0; j < 8; j++) acc[i][j] = 0.f;

    for (int k0 = 0; k0 < K; k0 += 8) {
#pragma unroll
        for (int i = 0; i < 4; i++) {
            int idx = tid + i * 256;
            int m = idx >> 3, kk = idx & 7;
            int gm = bm + m;
            As[kk][m] = (gm < M) ? Ab[(ll)gm * lda + k0 + kk] : 0.f;
        }
#pragma unroll
        for (int i = 0; i < 4; i++) {
            int idx = tid + i * 256;
            if (TRANSB) {
                int n = idx >> 3, kk = idx & 7;
                int gn = bn + n;
                Bs[kk][n] = (gn < N) ? Bb[(ll)gn * ldb + k0 + kk] : 0.f;
            } else {
                int kk = idx >> 7, n = idx & 127;
                int gn = bn + n;
                Bs[kk][n] = (gn < N) ? Bb[(ll)(k0 + kk) * ldb + gn] : 0.f;
            }
        }
        __syncthreads();

#pragma unroll
        for (int kk = 0; kk < 8; kk++) {
            float a[8], b[8];
#pragma unroll
            for (int i = 0; i < 8; i++) a[i] = As[kk][ty * 8 + i];
#pragma unroll
            for (int j = 0; j < 8; j++) b[j] = Bs[kk][tx * 8 + j];
#pragma unroll
            for (int i = 0; i < 8; i++)
#pragma unroll
                for (int j = 0; j < 8; j++) acc[i][j] += a[i] * b[j];
        }
        __syncthreads();
    }

#pragma unroll
    for (int i = 0; i < 8; i++) {
        int r = bm + ty * 8 + i;
        if (r >= M) continue;
#pragma unroll
        for (int j = 0; j < 8; j++) {
            int c = bn + tx * 8 + j;
            if (c >= N) continue;
            float v = acc[i][j];
            if (Rb) v += Rb[(ll)r * ldc + c];
            Cb[(ll)r * ldc + c] = v;
        }
    }
}

// ----------------------------------------------------------------------------
// Grouped (per-expert) SGEMM for MoE. Rows for expert e = [offs[e], offs[e]+counts[e]).
// A row index optionally gathered through rowidx. C rows are global slot indices.
// ----------------------------------------------------------------------------
__global__ __launch_bounds__(256) void grouped_gemm_nn(
    const float* __restrict__ A, int lda, const int* __restrict__ rowidx,
    const float* __restrict__ B, int ldb, ll sB,
    float* __restrict__ C, int ldc,
    int N, int K)
{
    const int e = blockIdx.z;
    const int cnt = g_counts[e];
    const int bm = blockIdx.y * 128;
    if (bm >= cnt) return;
    const int off = g_offs[e];
    const int bn = blockIdx.x * 128;

    const float* Bb = B + (ll)e * sB;
    const int tid = threadIdx.x;
    const int tx = tid & 15, ty = tid >> 4;

    __shared__ float As[8][128];
    __shared__ float Bs[8][128];

    // Resolve the (up to) 4 A-row pointers this thread loads
    const float* aptr[4];
    bool av[4];
#pragma unroll
    for (int i = 0; i < 4; i++) {
        int m = (tid + i * 256) >> 3;
        av[i] = (bm + m) < cnt;
        int gidx = off + bm + m;
        int ar = av[i] ? (rowidx ? rowidx[gidx] : gidx) : 0;
        aptr[i] = A + (ll)ar * lda;
    }

    float acc[8][8];
#pragma unroll
    for (int i = 0; i < 8; i++)
#pragma unroll
        for (int j = 0; j < 8; j++) acc[i][j] = 0.f;

    for (int k0 = 0; k0 < K; k0 += 8) {
#pragma unroll
        for (int i = 0; i < 4; i++) {
            int idx = tid + i * 256;
            int m = idx >> 3, kk = idx & 7;
            As[kk][m] = av[i] ? aptr[i][k0 + kk] : 0.f;
        }
#pragma unroll
        for (int i = 0; i < 4; i++) {
            int idx = tid + i * 256;
            int kk = idx >> 7, n = idx & 127;
            int gn = bn + n;
            Bs[kk][n] = (gn < N) ? Bb[(ll)(k0 + kk) * ldb + gn] : 0.f;
        }
        __syncthreads();

#pragma unroll
        for (int kk = 0; kk < 8; kk++) {
            float a[8], b[8];
#pragma unroll
            for (int i = 0; i < 8; i++) a[i] = As[kk][ty * 8 + i];
#pragma unroll
            for (int j = 0; j < 8; j++) b[j] = Bs[kk][tx * 8 + j];
#pragma unroll
            for (int i = 0; i < 8; i++)
#pragma unroll
                for (int j = 0; j < 8; j++) acc[i][j] += a[i] * b[j];
        }
        __syncthreads();
    }

#pragma unroll
    for (int i = 0; i < 8; i++) {
        int r = bm + ty * 8 + i;
        if (r >= cnt) continue;
#pragma unroll
        for (int j = 0; j < 8; j++) {
            int c = bn + tx * 8 + j;
            if (c >= N) continue;
            C[(ll)(off + r) * ldc + c] = acc[i][j];
        }
    }
}

// ----------------------------------------------------------------------------
// Small kernels
// ----------------------------------------------------------------------------
__global__ void embed_kernel(const int* __restrict__ ids, const float* __restrict__ tok)
{
    int t = blockIdx.x;
    ll base = (ll)ids[t] * DD;
    for (int d = threadIdx.x; d < DD; d += blockDim.x)
        g_x[t * DD + d] = tok[base + d];
}

__global__ void rmsnorm_kernel(const float* __restrict__ x, const float* __restrict__ w,
                               float* __restrict__ out)
{
    int t = blockIdx.x, tid = threadIdx.x;
    __shared__ float red[256];
    float s = 0.f;
    for (int d = tid; d < DD; d += 256) { float v = x[t * DD + d]; s += v * v; }
    red[tid] = s; __syncthreads();
    for (int st = 128; st > 0; st >>= 1) {
        if (tid < st) red[tid] += red[tid + st];
        __syncthreads();
    }
    float r = rsqrtf(red[0] / (float)DD + 1e-6f);
    for (int d = tid; d < DD; d += 256)
        out[t * DD + d] = x[t * DD + d] * r * w[d];
}

__global__ void rope_kernel()
{
    int t = blockIdx.x;
    int tid = threadIdx.x;          // 256 = H * HD/2
    int h = tid >> 5, i = tid & 31;
    float inv = powf(10000.f, -(float)i / 32.f);
    float ang = (float)t * inv;
    float c = cosf(ang), s = sinf(ang);
    int i1 = t * DD + h * HDD + i;
    int i2 = i1 + 32;
    float q1 = g_q[i1], q2 = g_q[i2];
    g_q[i1] = q1 * c - q2 * s;
    g_q[i2] = q2 * c + q1 * s;
    float k1 = g_k[i1], k2 = g_k[i2];
    g_k[i1] = k1 * c - k2 * s;
    g_k[i2] = k2 * c + k1 * s;
}

__global__ void attn_softmax_kernel()
{
    int b = blockIdx.x;
    int h = b / TT, t = b % TT;
    float* row = g_P + (ll)h * TT * TT + (ll)t * TT;
    const float scale = 0.125f;      // 1/sqrt(64)
    __shared__ float red[128];
    int tid = threadIdx.x;

    float m = -3.4e38f;
    for (int s = tid; s <= t; s += 128) m = fmaxf(m, row[s] * scale);
    red[tid] = m; __syncthreads();
    for (int st = 64; st > 0; st >>= 1) {
        if (tid < st) red[tid] = fmaxf(red[tid], red[tid + st]);
        __syncthreads();
    }
    m = red[0]; __syncthreads();

    float sum = 0.f;
    for (int s = tid; s <= t; s += 128) {
        float e = expf(row[s] * scale - m);
        row[s] = e; sum += e;
    }
    red[tid] = sum; __syncthreads();
    for (int st = 64; st > 0; st >>= 1) {
        if (tid < st) red[tid] += red[tid + st];
        __syncthreads();
    }
    float inv = 1.f / red[0];
    for (int s = tid; s <= t; s += 128) row[s] *= inv;
    for (int s = t + 1 + tid; s < TT; s += 128) row[s] = 0.f;
}

__global__ void zero_counts_kernel()
{
    if (threadIdx.x < EE) g_counts[threadIdx.x] = 0;
}

__global__ void router_kernel(const float* __restrict__ xn, const float* __restrict__ rw)
{
    int t = blockIdx.x, tid = threadIdx.x;    // 128 threads
    __shared__ float part[EE][128];
    float loc[EE];
#pragma unroll
    for (int e = 0; e < EE; e++) loc[e] = 0.f;
    for (int d = tid; d < DD; d += 128) {
        float xv = xn[t * DD + d];
#pragma unroll
        for (int e = 0; e < EE; e++) loc[e] += xv * rw[d * EE + e];
    }
#pragma unroll
    for (int e = 0; e < EE; e++) part[e][tid] = loc[e];
    __syncthreads();
    for (int st = 64; st > 0; st >>= 1) {
        if (tid < st)
#pragma unroll
            for (int e = 0; e < EE; e++) part[e][tid] += part[e][tid + st];
        __syncthreads();
    }
    if (tid == 0) {
        float v0 = -3.4e38f, v1 = -3.4e38f;
        int i0 = 0, i1 = 0;
        for (int e = 0; e < EE; e++) {
            float v = part[e][0];
            if (v > v0) { v1 = v0; i1 = i0; v0 = v; i0 = e; }
            else if (v > v1) { v1 = v; i1 = e; }
        }
        float e1 = expf(v1 - v0);
        float inv = 1.f / (1.f + e1);
        g_eidx[t * 2]     = i0;  g_ew[t * 2]     = inv;
        g_eidx[t * 2 + 1] = i1;  g_ew[t * 2 + 1] = e1 * inv;
        atomicAdd(&g_counts[i0], 1);
        atomicAdd(&g_counts[i1], 1);
    }
}

__global__ void scan_kernel()
{
    int off = 0;
    for (int e = 0; e < EE; e++) {
        g_offs[e] = off;
        off += g_counts[e];
        g_cursor[e] = 0;
    }
}

__global__ void scatter_kernel()
{
    int idx = blockIdx.x * blockDim.x + threadIdx.x;
    if (idx >= TT * KEXP) return;
    int e = g_eidx[idx];
    int pos = g_offs[e] + atomicAdd(&g_cursor[e], 1);
    g_perm[pos] = idx >> 1;
    g_slot[idx] = pos;
}

__global__ void silu_mul_kernel()
{
    int i = blockIdx.x * blockDim.x + threadIdx.x;
    if (i >= TT * KEXP * HIDN) return;
    float g = g_G[i];
    g_G[i] = (g / (1.f + expf(-g))) * g_U[i];
}

__global__ void combine_kernel()
{
    int i = blockIdx.x * blockDim.x + threadIdx.x;
    if (i >= TT * DD) return;
    int t = i / DD, d = i % DD;
    int s0 = g_slot[t * 2], s1 = g_slot[t * 2 + 1];
    float acc = g_ew[t * 2] * g_Y[(ll)s0 * DD + d]
              + g_ew[t * 2 + 1] * g_Y[(ll)s1 * DD + d];
    g_x[i] += acc;
}

// ----------------------------------------------------------------------------
// Orchestration
// ----------------------------------------------------------------------------
extern "C" void kernel_launch(void* const* d_in, const int* in_sizes, int n_in,
                              void* d_out, int out_size)
{
    const int*   ids     = (const int*)d_in[0];
    const float* tok     = (const float*)d_in[1];
    const float* attn_nw = (const float*)d_in[2];
    const float* wq      = (const float*)d_in[3];
    const float* wk      = (const float*)d_in[4];
    const float* wv      = (const float*)d_in[5];
    const float* wo      = (const float*)d_in[6];
    const float* moe_nw  = (const float*)d_in[7];
    const float* rw      = (const float*)d_in[8];
    const float* w1      = (const float*)d_in[9];
    const float* w2      = (const float*)d_in[10];
    const float* w3      = (const float*)d_in[11];
    const float* fnw     = (const float*)d_in[12];
    float*       out     = (float*)d_out;

    float *x, *xn, *q, *k, *v, *attn, *P, *G, *U, *Y;
    int* perm;
    cudaGetSymbolAddress((void**)&x,    g_x);
    cudaGetSymbolAddress((void**)&xn,   g_xn);
    cudaGetSymbolAddress((void**)&q,    g_q);
    cudaGetSymbolAddress((void**)&k,    g_k);
    cudaGetSymbolAddress((void**)&v,    g_v);
    cudaGetSymbolAddress((void**)&attn, g_attn);
    cudaGetSymbolAddress((void**)&P,    g_P);
    cudaGetSymbolAddress((void**)&G,    g_G);
    cudaGetSymbolAddress((void**)&U,    g_U);
    cudaGetSymbolAddress((void**)&Y,    g_Y);
    cudaGetSymbolAddress((void**)&perm, g_perm);

    embed_kernel<<<TT, 256>>>(ids, tok);

    for (int l = 0; l < LLAY; l++) {
        // Attention block
        rmsnorm_kernel<<<TT, 256>>>(x, attn_nw + (ll)l * DD, xn);

        dim3 gp(4, 16, 1);
        sgemm_kernel<false><<<gp, 256>>>(xn, DD, 0, wq + (ll)l * DD * DD, DD, 0,
                                         q, DD, 0, (const float*)0, TT, DD, DD, 0);
        sgemm_kernel<false><<<gp, 256>>>(xn, DD, 0, wk + (ll)l * DD * DD, DD, 0,
                                         k, DD, 0, (const float*)0, TT, DD, DD, 0);
        sgemm_kernel<false><<<gp, 256>>>(xn, DD, 0, wv + (ll)l * DD * DD, DD, 0,
                                         v, DD, 0, (const float*)0, TT, DD, DD, 0);

        rope_kernel<<<TT, 256>>>();

        // scores = q @ k^T per head (causal: upper tiles skipped)
        dim3 gs(16, 16, HH);
        sgemm_kernel<true><<<gs, 256>>>(q, DD, HDD, k, DD, HDD,
                                        P, TT, (ll)TT * TT, (const float*)0,
                                        TT, TT, HDD, 1);
        attn_softmax_kernel<<<HH * TT, 128>>>();

        // attn = P @ v per head
        dim3 ga(1, 16, HH);
        sgemm_kernel<false><<<ga, 256>>>(P, TT, (ll)TT * TT, v, DD, HDD,
                                         attn, DD, HDD, (const float*)0,
                                         TT, HDD, TT, 0);

        // x = x + attn @ wo
        sgemm_kernel<false><<<gp, 256>>>(attn, DD, 0, wo + (ll)l * DD * DD, DD, 0,
                                         x, DD, 0, x, TT, DD, DD, 0);

        // MoE block
        rmsnorm_kernel<<<TT, 256>>>(x, moe_nw + (ll)l * DD, xn);
        zero_counts_kernel<<<1, 32>>>();
        router_kernel<<<TT, 128>>>(xn, rw + (ll)l * DD * EE);
        scan_kernel<<<1, 1>>>();
        scatter_kernel<<<(TT * KEXP + 255) / 256, 256>>>();

        dim3 gg(16, 16, EE);
        grouped_gemm_nn<<<gg, 256>>>(xn, DD, perm,
                                     w1 + (ll)l * EE * DD * HIDN, HIDN, (ll)DD * HIDN,
                                     G, HIDN, HIDN, DD);
        grouped_gemm_nn<<<gg, 256>>>(xn, DD, perm,
                                     w3 + (ll)l * EE * DD * HIDN, HIDN, (ll)DD * HIDN,
                                     U, HIDN, HIDN, DD);
        silu_mul_kernel<<<(TT * KEXP * HIDN + 255) / 256, 256>>>();

        dim3 gy(4, 16, EE);
        grouped_gemm_nn<<<gy, 256>>>(G, HIDN, (const int*)0,
                                     w2 + (ll)l * EE * HIDN * DD, DD, (ll)HIDN * DD,
                                     Y, DD, DD, HIDN);
        combine_kernel<<<(TT * DD + 255) / 256, 256>>>();
    }

    // Final norm + LM head: out = xn @ tok^T
    rmsnorm_kernel<<<TT, 256>>>(x, fnw, xn);
    dim3 gl(250, 16, 1);
    sgemm_kernel<true><<<gl, 256>>>(xn, DD, 0, tok, DD, 0,
                                    out, VV, 0, (const float*)0, TT, VV, DD, 0);
}

// round 8
// speedup vs baseline: 1.1000x; 1.1000x over previous
#include <cuda_runtime.h>
#include <math.h>
#include <stdint.h>

#define TT   2048
#define DD   512
#define HH   8
#define HDD  64
#define LLAY 4
#define HIDN 2048
#define EE   8
#define VV   32000
typedef long long ll;
typedef unsigned long long ull;

// ---------------- device scratch ----------------
__device__ float g_x[TT * DD];
__device__ float g_xn[TT * DD];
__device__ float g_q[TT * DD];
__device__ float g_k[TT * DD];
__device__ float g_v[TT * DD];
__device__ float g_attn[TT * DD];
__device__ float g_P[(ll)HH * TT * TT];
__device__ float g_G[TT * 2 * HIDN];
__device__ float g_U[TT * 2 * HIDN];
__device__ float g_Y[TT * 2 * DD];
__device__ float g_ew[TT * 2];
__device__ int   g_eidx[TT * 2];
__device__ int   g_counts[EE];
__device__ int   g_offs[EE];
__device__ int   g_cursor[EE];
__device__ int   g_perm[TT * 2];
__device__ int   g_slot[TT * 2];

// ---------------- f32x2 helpers (sm_100+, non-arch-specific) ----------------
__device__ __forceinline__ ull pk2(float x) {
    ull r; uint32_t u = __float_as_uint(x);
    asm("mov.b64 %0, {%1, %1};" : "=l"(r) : "r"(u));
    return r;
}
__device__ __forceinline__ float2 up2(ull v) {
    uint32_t lo, hi;
    asm("mov.b64 {%0, %1}, %2;" : "=r"(lo), "=r"(hi) : "l"(v));
    return make_float2(__uint_as_float(lo), __uint_as_float(hi));
}
#define FMA2(c, a, b) asm("fma.rn.f32x2 %0, %1, %2, %0;" : "+l"(c) : "l"(a), "l"(b))

// 8x8 per-thread tile as 8 rows x 4 col-pairs; bit-identical to scalar FFMA.
__device__ __forceinline__ void micro8(
    const float (*As)[128], const float (*Bs)[128],
    ull c[8][4], int ty, int tx)
{
#pragma unroll
    for (int kk = 0; kk < 8; kk++) {
        const float* ar = &As[kk][ty * 8];
        const ull* br = (const ull*)&Bs[kk][tx * 8];
        ull b0 = br[0], b1 = br[1], b2 = br[2], b3 = br[3];
#pragma unroll
        for (int i = 0; i < 8; i++) {
            ull ap = pk2(ar[i]);
            FMA2(c[i][0], ap, b0);
            FMA2(c[i][1], ap, b1);
            FMA2(c[i][2], ap, b2);
            FMA2(c[i][3], ap, b3);
        }
    }
}

#define FLAG_CAUSAL 1
#define FLAG_KCLIP  2

// ---------------- generic batched GEMM (round-1 layout, f32x2 core) --------
// C = A @ B (or A @ B^T), optional residual. M = gridDim.y*128 covered.
template <bool TRANSB>
__global__ __launch_bounds__(256, 2) void sgemm2(
    const float* __restrict__ A, int lda, ll sA,
    const float* __restrict__ B, int ldb, ll sB,
    float* __restrict__ C, int ldc, ll sC,
    const float* __restrict__ Res,
    int M, int N, int K, int flags)
{
    if ((flags & FLAG_CAUSAL) && (int)blockIdx.x > (int)blockIdx.y) return;

    const float* Ab = A + (ll)blockIdx.z * sA;
    const float* Bb = B + (ll)blockIdx.z * sB;
    float*       Cb = C + (ll)blockIdx.z * sC;
    const float* Rb = Res ? (Res + (ll)blockIdx.z * sC) : (const float*)0;

    const int bm = blockIdx.y * 128, bn = blockIdx.x * 128;
    const int tid = threadIdx.x;
    const int tx = tid & 15, ty = tid >> 4;

    __shared__ __align__(16) float As[8][128];
    __shared__ __align__(16) float Bs[8][128];

    ull c[8][4];
#pragma unroll
    for (int i = 0; i < 8; i++)
#pragma unroll
        for (int j = 0; j < 4; j++) c[i][j] = 0ull;

    const int kmax = (flags & FLAG_KCLIP) ? min(K, bm + 128) : K;

    for (int k0 = 0; k0 < kmax; k0 += 8) {
#pragma unroll
        for (int i = 0; i < 4; i++) {
            int idx = tid + i * 256;
            int m = idx >> 3, kk = idx & 7;
            int gm = bm + m;
            As[kk][m] = (gm < M) ? Ab[(ll)gm * lda + k0 + kk] : 0.f;
        }
#pragma unroll
        for (int i = 0; i < 4; i++) {
            int idx = tid + i * 256;
            if (TRANSB) {
                int n = idx >> 3, kk = idx & 7;
                int gn = bn + n;
                Bs[kk][n] = (gn < N) ? Bb[(ll)gn * ldb + k0 + kk] : 0.f;
            } else {
                int kk = idx >> 7, n = idx & 127;
                int gn = bn + n;
                Bs[kk][n] = (gn < N) ? Bb[(ll)(k0 + kk) * ldb + gn] : 0.f;
            }
        }
        __syncthreads();
        micro8(As, Bs, c, ty, tx);
        __syncthreads();
    }

#pragma unroll
    for (int i = 0; i < 8; i++) {
        int r = bm + ty * 8 + i;
        if (r >= M) continue;
#pragma unroll
        for (int j = 0; j < 4; j++) {
            int cc = bn + tx * 8 + j * 2;
            float2 v = up2(c[i][j]);
            if (cc < N) {
                float o = v.x;
                if (Rb) o += Rb[(ll)r * ldc + cc];
                Cb[(ll)r * ldc + cc] = o;
            }
            if (cc + 1 < N) {
                float o = v.y;
                if (Rb) o += Rb[(ll)r * ldc + cc + 1];
                Cb[(ll)r * ldc + cc + 1] = o;
            }
        }
    }
}

// ---------------- fused QKV: z selects weight/output ----------------
__global__ __launch_bounds__(256, 2) void qkv_gemm(
    const float* __restrict__ xn,
    const float* __restrict__ wq, const float* __restrict__ wk,
    const float* __restrict__ wv, int l)
{
    const int z = blockIdx.z;
    const float* Bb = (z == 0 ? wq : z == 1 ? wk : wv) + (ll)l * DD * DD;
    float* Cb = (z == 0 ? g_q : z == 1 ? g_k : g_v);

    const int bm = blockIdx.y * 128, bn = blockIdx.x * 128;
    const int tid = threadIdx.x;
    const int tx = tid & 15, ty = tid >> 4;

    __shared__ __align__(16) float As[8][128];
    __shared__ __align__(16) float Bs[8][128];

    ull c[8][4];
#pragma unroll
    for (int i = 0; i < 8; i++)
#pragma unroll
        for (int j = 0; j < 4; j++) c[i][j] = 0ull;

    for (int k0 = 0; k0 < DD; k0 += 8) {
#pragma unroll
        for (int i = 0; i < 4; i++) {
            int idx = tid + i * 256;
            int m = idx >> 3, kk = idx & 7;
            As[kk][m] = xn[(ll)(bm + m) * DD + k0 + kk];
        }
#pragma unroll
        for (int i = 0; i < 4; i++) {
            int idx = tid + i * 256;
            int kk = idx >> 7, n = idx & 127;
            Bs[kk][n] = Bb[(ll)(k0 + kk) * DD + bn + n];
        }
        __syncthreads();
        micro8(As, Bs, c, ty, tx);
        __syncthreads();
    }

#pragma unroll
    for (int i = 0; i < 8; i++) {
        int r = bm + ty * 8 + i;
#pragma unroll
        for (int j = 0; j < 4; j++) {
            int cc = bn + tx * 8 + j * 2;
            float2 v = up2(c[i][j]);
            Cb[(ll)r * DD + cc]     = v.x;
            Cb[(ll)r * DD + cc + 1] = v.y;
        }
    }
}

// ---------------- fused MoE up (w1 & w3 via z), grouped + gathered --------
__global__ __launch_bounds__(256, 2) void moeup_gemm(
    const float* __restrict__ xn,
    const float* __restrict__ w1, const float* __restrict__ w3, int l)
{
    const int e = blockIdx.z >> 1, which = blockIdx.z & 1;
    const int cnt = g_counts[e];
    const int bm = blockIdx.y * 128;
    if (bm >= cnt) return;
    const int off = g_offs[e];
    const int bn = blockIdx.x * 128;

    const float* Bb = (which ? w3 : w1) + ((ll)l * EE + e) * DD * HIDN;
    float* Cb = which ? g_U : g_G;

    const int tid = threadIdx.x;
    const int tx = tid & 15, ty = tid >> 4;

    __shared__ __align__(16) float As[8][128];
    __shared__ __align__(16) float Bs[8][128];

    const float* aptr[4];
    int av[4];
#pragma unroll
    for (int i = 0; i < 4; i++) {
        int m = (tid + i * 256) >> 3;
        av[i] = (bm + m) < cnt;
        aptr[i] = xn + (ll)(av[i] ? g_perm[off + bm + m] : 0) * DD;
    }

    ull c[8][4];
#pragma unroll
    for (int i = 0; i < 8; i++)
#pragma unroll
        for (int j = 0; j < 4; j++) c[i][j] = 0ull;

    for (int k0 = 0; k0 < DD; k0 += 8) {
#pragma unroll
        for (int i = 0; i < 4; i++) {
            int idx = tid + i * 256;
            int m = idx >> 3, kk = idx & 7;
            As[kk][m] = av[i] ? aptr[i][k0 + kk] : 0.f;
        }
#pragma unroll
        for (int i = 0; i < 4; i++) {
            int idx = tid + i * 256;
            int kk = idx >> 7, n = idx & 127;
            Bs[kk][n] = Bb[(ll)(k0 + kk) * HIDN + bn + n];
        }
        __syncthreads();
        micro8(As, Bs, c, ty, tx);
        __syncthreads();
    }

#pragma unroll
    for (int i = 0; i < 8; i++) {
        int r = bm + ty * 8 + i;
        if (r >= cnt) continue;
#pragma unroll
        for (int j = 0; j < 4; j++) {
            int cc = bn + tx * 8 + j * 2;
            float2 v = up2(c[i][j]);
            Cb[(ll)(off + r) * HIDN + cc]     = v.x;
            Cb[(ll)(off + r) * HIDN + cc + 1] = v.y;
        }
    }
}

// ---------------- MoE down: Y = G @ w2 (grouped, contiguous rows) ----------
__global__ __launch_bounds__(256, 2) void moedown_gemm(const float* __restrict__ w2, int l)
{
    const int e = blockIdx.z;
    const int cnt = g_counts[e];
    const int bm = blockIdx.y * 128;
    if (bm >= cnt) return;
    const int off = g_offs[e];
    const int bn = blockIdx.x * 128;

    const float* Bb = w2 + ((ll)l * EE + e) * HIDN * DD;

    const int tid = threadIdx.x;
    const int tx = tid & 15, ty = tid >> 4;

    __shared__ __align__(16) float As[8][128];
    __shared__ __align__(16) float Bs[8][128];

    ull c[8][4];
#pragma unroll
    for (int i = 0; i < 8; i++)
#pragma unroll
        for (int j = 0; j < 4; j++) c[i][j] = 0ull;

    for (int k0 = 0; k0 < HIDN; k0 += 8) {
#pragma unroll
        for (int i = 0; i < 4; i++) {
            int idx = tid + i * 256;
            int m = idx >> 3, kk = idx & 7;
            As[kk][m] = ((bm + m) < cnt) ? g_G[(ll)(off + bm + m) * HIDN + k0 + kk] : 0.f;
        }
#pragma unroll
        for (int i = 0; i < 4; i++) {
            int idx = tid + i * 256;
            int kk = idx >> 7, n = idx & 127;
            Bs[kk][n] = Bb[(ll)(k0 + kk) * DD + bn + n];
        }
        __syncthreads();
        micro8(As, Bs, c, ty, tx);
        __syncthreads();
    }

#pragma unroll
    for (int i = 0; i < 8; i++) {
        int r = bm + ty * 8 + i;
        if (r >= cnt) continue;
#pragma unroll
        for (int j = 0; j < 4; j++) {
            int cc = bn + tx * 8 + j * 2;
            float2 v = up2(c[i][j]);
            g_Y[(ll)(off + r) * DD + cc]     = v.x;
            g_Y[(ll)(off + r) * DD + cc + 1] = v.y;
        }
    }
}

// ---------------- small kernels (round-1 proven versions) ----------------
__global__ void embed_kernel(const int* __restrict__ ids, const float* __restrict__ tok)
{
    int t = blockIdx.x;
    ll base = (ll)ids[t] * DD;
    for (int d = threadIdx.x; d < DD; d += blockDim.x)
        g_x[t * DD + d] = tok[base + d];
}

__global__ void rmsnorm_kernel(const float* __restrict__ x, const float* __restrict__ w,
                               float* __restrict__ out)
{
    int t = blockIdx.x, tid = threadIdx.x;
    __shared__ float red[256];
    float s = 0.f;
    for (int d = tid; d < DD; d += 256) { float v = x[t * DD + d]; s += v * v; }
    red[tid] = s; __syncthreads();
    for (int st = 128; st > 0; st >>= 1) {
        if (tid < st) red[tid] += red[tid + st];
        __syncthreads();
    }
    float r = rsqrtf(red[0] / (float)DD + 1e-6f);
    for (int d = tid; d < DD; d += 256)
        out[t * DD + d] = x[t * DD + d] * r * w[d];
}

__global__ void rope_kernel()
{
    int t = blockIdx.x, tid = threadIdx.x;
    int h = tid >> 5, i = tid & 31;
    float inv = powf(10000.f, -(float)i / 32.f);
    float ang = (float)t * inv;
    float c = cosf(ang), s = sinf(ang);
    int i1 = t * DD + h * HDD + i, i2 = i1 + 32;
    float q1 = g_q[i1], q2 = g_q[i2];
    g_q[i1] = q1 * c - q2 * s;
    g_q[i2] = q2 * c + q1 * s;
    float k1 = g_k[i1], k2 = g_k[i2];
    g_k[i1] = k1 * c - k2 * s;
    g_k[i2] = k2 * c + k1 * s;
}

__global__ void attn_softmax_kernel()
{
    int b = blockIdx.x;
    int h = b / TT, t = b % TT;
    float* row = g_P + (ll)h * TT * TT + (ll)t * TT;
    const float scale = 0.125f;
    __shared__ float red[128];
    int tid = threadIdx.x;

    float m = -3.4e38f;
    for (int s = tid; s <= t; s += 128) m = fmaxf(m, row[s] * scale);
    red[tid] = m; __syncthreads();
    for (int st = 64; st > 0; st >>= 1) {
        if (tid < st) red[tid] = fmaxf(red[tid], red[tid + st]);
        __syncthreads();
    }
    m = red[0]; __syncthreads();

    float sum = 0.f;
    for (int s = tid; s <= t; s += 128) {
        float e = expf(row[s] * scale - m);
        row[s] = e; sum += e;
    }
    red[tid] = sum; __syncthreads();
    for (int st = 64; st > 0; st >>= 1) {
        if (tid < st) red[tid] += red[tid + st];
        __syncthreads();
    }
    float inv = 1.f / red[0];
    for (int s = tid; s <= t; s += 128) row[s] *= inv;
    for (int s = t + 1 + tid; s < TT; s += 128) row[s] = 0.f;
}

__global__ void zero_counts_kernel()
{
    if (threadIdx.x < EE) g_counts[threadIdx.x] = 0;
}

__global__ void router_kernel(const float* __restrict__ xn, const float* __restrict__ rw)
{
    int t = blockIdx.x, tid = threadIdx.x;
    __shared__ float part[EE][128];
    float loc[EE];
#pragma unroll
    for (int e = 0; e < EE; e++) loc[e] = 0.f;
    for (int d = tid; d < DD; d += 128) {
        float xv = xn[t * DD + d];
#pragma unroll
        for (int e = 0; e < EE; e++) loc[e] += xv * rw[d * EE + e];
    }
#pragma unroll
    for (int e = 0; e < EE; e++) part[e][tid] = loc[e];
    __syncthreads();
    for (int st = 64; st > 0; st >>= 1) {
        if (tid < st)
#pragma unroll
            for (int e = 0; e < EE; e++) part[e][tid] += part[e][tid + st];
        __syncthreads();
    }
    if (tid == 0) {
        float v0 = -3.4e38f, v1 = -3.4e38f;
        int i0 = 0, i1 = 0;
        for (int e = 0; e < EE; e++) {
            float v = part[e][0];
            if (v > v0) { v1 = v0; i1 = i0; v0 = v; i0 = e; }
            else if (v > v1) { v1 = v; i1 = e; }
        }
        float e1 = expf(v1 - v0);
        float inv = 1.f / (1.f + e1);
        g_eidx[t * 2]     = i0;  g_ew[t * 2]     = inv;
        g_eidx[t * 2 + 1] = i1;  g_ew[t * 2 + 1] = e1 * inv;
        atomicAdd(&g_counts[i0], 1);
        atomicAdd(&g_counts[i1], 1);
    }
}

__global__ void scan_kernel()
{
    int off = 0;
    for (int e = 0; e < EE; e++) {
        g_offs[e] = off;
        off += g_counts[e];
        g_cursor[e] = 0;
    }
}

__global__ void scatter_kernel()
{
    int idx = blockIdx.x * blockDim.x + threadIdx.x;
    if (idx >= TT * 2) return;
    int e = g_eidx[idx];
    int pos = g_offs[e] + atomicAdd(&g_cursor[e], 1);
    g_perm[pos] = idx >> 1;
    g_slot[idx] = pos;
}

__global__ void silu_mul_kernel()
{
    int i = blockIdx.x * blockDim.x + threadIdx.x;
    if (i >= TT * 2 * HIDN) return;
    float g = g_G[i];
    g_G[i] = (g / (1.f + expf(-g))) * g_U[i];
}

__global__ void combine_kernel()
{
    int i = blockIdx.x * blockDim.x + threadIdx.x;
    if (i >= TT * DD) return;
    int t = i / DD, d = i % DD;
    g_x[i] += g_ew[t * 2] * g_Y[(ll)g_slot[t * 2] * DD + d]
            + g_ew[t * 2 + 1] * g_Y[(ll)g_slot[t * 2 + 1] * DD + d];
}

// ---------------- orchestration ----------------
extern "C" void kernel_launch(void* const* d_in, const int* in_sizes, int n_in,
                              void* d_out, int out_size)
{
    const int*   ids     = (const int*)d_in[0];
    const float* tok     = (const float*)d_in[1];
    const float* attn_nw = (const float*)d_in[2];
    const float* wq      = (const float*)d_in[3];
    const float* wk      = (const float*)d_in[4];
    const float* wv      = (const float*)d_in[5];
    const float* wo      = (const float*)d_in[6];
    const float* moe_nw  = (const float*)d_in[7];
    const float* rw      = (const float*)d_in[8];
    const float* w1      = (const float*)d_in[9];
    const float* w2      = (const float*)d_in[10];
    const float* w3      = (const float*)d_in[11];
    const float* fnw     = (const float*)d_in[12];
    float*       out     = (float*)d_out;

    float *x, *xn, *q, *k, *v, *attn, *P;
    cudaGetSymbolAddress((void**)&x,    g_x);
    cudaGetSymbolAddress((void**)&xn,   g_xn);
    cudaGetSymbolAddress((void**)&q,    g_q);
    cudaGetSymbolAddress((void**)&k,    g_k);
    cudaGetSymbolAddress((void**)&v,    g_v);
    cudaGetSymbolAddress((void**)&attn, g_attn);
    cudaGetSymbolAddress((void**)&P,    g_P);

    embed_kernel<<<TT, 256>>>(ids, tok);

    for (int l = 0; l < LLAY; l++) {
        // ---- attention ----
        rmsnorm_kernel<<<TT, 256>>>(x, attn_nw + (ll)l * DD, xn);

        qkv_gemm<<<dim3(4, 16, 3), 256>>>(xn, wq, wk, wv, l);
        rope_kernel<<<TT, 256>>>();

        // scores = q @ k^T per head (causal block-skip)
        sgemm2<true><<<dim3(16, 16, HH), 256>>>(q, DD, HDD, k, DD, HDD,
                                                P, TT, (ll)TT * TT, (const float*)0,
                                                TT, TT, HDD, FLAG_CAUSAL);
        attn_softmax_kernel<<<HH * TT, 128>>>();

        // attn = P @ v  (exact-zero columns skipped via KCLIP)
        sgemm2<false><<<dim3(1, 16, HH), 256>>>(P, TT, (ll)TT * TT, v, DD, HDD,
                                                attn, DD, HDD, (const float*)0,
                                                TT, HDD, TT, FLAG_KCLIP);

        // x += attn @ wo
        sgemm2<false><<<dim3(4, 16, 1), 256>>>(attn, DD, 0, wo + (ll)l * DD * DD, DD, 0,
                                               x, DD, 0, x, TT, DD, DD, 0);

        // ---- MoE ----
        rmsnorm_kernel<<<TT, 256>>>(x, moe_nw + (ll)l * DD, xn);
        zero_counts_kernel<<<1, 32>>>();
        router_kernel<<<TT, 128>>>(xn, rw + (ll)l * DD * EE);
        scan_kernel<<<1, 1>>>();
        scatter_kernel<<<(TT * 2 + 255) / 256, 256>>>();

        moeup_gemm<<<dim3(16, 16, 16), 256>>>(xn, w1, w3, l);
        silu_mul_kernel<<<(TT * 2 * HIDN + 255) / 256, 256>>>();
        moedown_gemm<<<dim3(4, 16, EE), 256>>>(w2, l);
        combine_kernel<<<(TT * DD + 255) / 256, 256>>>();
    }

    // ---- final norm + LM head ----
    rmsnorm_kernel<<<TT, 256>>>(x, fnw, xn);
    sgemm2<true><<<dim3(250, 16, 1), 256>>>(xn, DD, 0, tok, DD, 0,
                                            out, VV, 0, (const float*)0,
                                            TT, VV, DD, 0);
}